// round 1
// baseline (speedup 1.0000x reference)
#include <cuda_runtime.h>
#include <cuda_bf16.h>
#include <mma.h>

using namespace nvcuda;

#define SDIM 512
#define NBATCH 512            // QLEN(128) * HEADS(4)
#define SCALE 0.044194173824159216f   // 1/sqrt(512)

#define BM 128
#define BN 128
#define BK 32
#define LDA 40      // smem stride (bf16) for 128x32 tiles, 80B rows (16B-multiple)
#define LDC 132     // smem stride (float) for 128x128 C tile
#define LDB2 136    // smem stride (bf16) for 32x128 V tile

// Scratch: E = exp(scale * Q K^T) for all 512 batches (bf16), partial column sums, 1/Z.
__device__ __nv_bfloat16 g_E[(size_t)NBATCH * SDIM * SDIM];   // 256 MB
__device__ float g_partZ[NBATCH][4][SDIM];                    // per-(batch, i-tile) column sums
__device__ float g_Zinv[NBATCH][SDIM];

// ---------------------------------------------------------------------------
// Kernel 1: S-tile = Q Kt (bf16 WMMA, fp32 accum), E = exp(scale*S) -> gmem,
//           deterministic per-tile column partial sums.
// grid: (16, 512)  blockIdx.x = it*4 + nt, blockIdx.y = batch. 256 threads.
// ---------------------------------------------------------------------------
__global__ void __launch_bounds__(256) k1_qk_exp(const float* __restrict__ Q,
                                                 const float* __restrict__ Km)
{
    extern __shared__ char smem_raw[];
    __nv_bfloat16* As = (__nv_bfloat16*)smem_raw;        // [BM][LDA]
    __nv_bfloat16* Bs = As + BM * LDA;                   // [BN][LDA]
    float* Cs = (float*)smem_raw;                        // aliased after mainloop [BM][LDC]

    const int batch = blockIdx.y;
    const int it = blockIdx.x >> 2;
    const int nt = blockIdx.x & 3;
    const float* Qb = Q  + (size_t)batch * SDIM * SDIM + (size_t)(it * BM) * SDIM;
    const float* Kb = Km + (size_t)batch * SDIM * SDIM + (size_t)(nt * BN) * SDIM;

    const int tid = threadIdx.x;
    const int wid = tid >> 5;
    const int wr = wid & 3;    // warp row group (32 rows)
    const int wc = wid >> 2;   // warp col group (64 cols)

    wmma::fragment<wmma::accumulator, 16, 16, 16, float> acc[2][4];
#pragma unroll
    for (int a = 0; a < 2; a++)
#pragma unroll
        for (int b = 0; b < 4; b++) wmma::fill_fragment(acc[a][b], 0.0f);

    const int lr = tid >> 3;          // 0..31
    const int lc = (tid & 7) << 2;    // 0,4,...,28

    for (int kk = 0; kk < SDIM; kk += BK) {
#pragma unroll
        for (int i = 0; i < 4; i++) {
            int row = lr + (i << 5);
            float4 qa = *(const float4*)(Qb + (size_t)row * SDIM + kk + lc);
            float4 ka = *(const float4*)(Kb + (size_t)row * SDIM + kk + lc);
            __nv_bfloat16* pa = As + row * LDA + lc;
            pa[0] = __float2bfloat16(qa.x); pa[1] = __float2bfloat16(qa.y);
            pa[2] = __float2bfloat16(qa.z); pa[3] = __float2bfloat16(qa.w);
            __nv_bfloat16* pb = Bs + row * LDA + lc;
            pb[0] = __float2bfloat16(ka.x); pb[1] = __float2bfloat16(ka.y);
            pb[2] = __float2bfloat16(ka.z); pb[3] = __float2bfloat16(ka.w);
        }
        __syncthreads();
#pragma unroll
        for (int ks = 0; ks < BK; ks += 16) {
            wmma::fragment<wmma::matrix_a, 16, 16, 16, __nv_bfloat16, wmma::row_major> af[2];
            wmma::fragment<wmma::matrix_b, 16, 16, 16, __nv_bfloat16, wmma::col_major> bf[4];
#pragma unroll
            for (int a = 0; a < 2; a++)
                wmma::load_matrix_sync(af[a], As + (wr * 32 + a * 16) * LDA + ks, LDA);
#pragma unroll
            for (int b = 0; b < 4; b++)
                wmma::load_matrix_sync(bf[b], Bs + (wc * 64 + b * 16) * LDA + ks, LDA);
#pragma unroll
            for (int a = 0; a < 2; a++)
#pragma unroll
                for (int b = 0; b < 4; b++)
                    wmma::mma_sync(acc[a][b], af[a], bf[b], acc[a][b]);
        }
        __syncthreads();
    }

    // Stage fp32 result tile to smem (aliases As/Bs; all reads done at this point).
#pragma unroll
    for (int a = 0; a < 2; a++)
#pragma unroll
        for (int b = 0; b < 4; b++)
            wmma::store_matrix_sync(Cs + (wr * 32 + a * 16) * LDC + wc * 64 + b * 16,
                                    acc[a][b], LDC, wmma::mem_row_major);
    __syncthreads();

    // exp + store E (bf16) + column partial sums (deterministic: fixed order).
    const int col = tid & 127;
    const int half = tid >> 7;
    __nv_bfloat16* Eb = g_E + (size_t)batch * SDIM * SDIM + (size_t)(it * BM) * SDIM + nt * BN;
    float zsum = 0.0f;
#pragma unroll 4
    for (int r = half * 64; r < half * 64 + 64; r++) {
        float e = __expf(Cs[r * LDC + col] * SCALE);
        zsum += e;
        Eb[(size_t)r * SDIM + col] = __float2bfloat16(e);
    }
    __shared__ float zs[2][128];
    zs[half][col] = zsum;
    __syncthreads();
    if (tid < 128)
        g_partZ[batch][it][nt * BN + tid] = zs[0][tid] + zs[1][tid];
}

// ---------------------------------------------------------------------------
// Kernel 1b: Z reduce -> 1/Z (deterministic fixed-order sum of 4 partials)
// ---------------------------------------------------------------------------
__global__ void __launch_bounds__(512) k_zred()
{
    int batch = blockIdx.x;
    int c = threadIdx.x;
    float z = g_partZ[batch][0][c] + g_partZ[batch][1][c]
            + g_partZ[batch][2][c] + g_partZ[batch][3][c];
    g_Zinv[batch][c] = 1.0f / z;
}

// ---------------------------------------------------------------------------
// Kernel 2: out = E @ (diag(1/Z) V). E bf16 in scratch; V fp32 scaled by 1/Z_k
// at load and converted to bf16. Output fp32 directly to d_out.
// grid: (16, 512) blockIdx.x = it*4 + jt. 256 threads.
// ---------------------------------------------------------------------------
__global__ void __launch_bounds__(256) k2_pv(const float* __restrict__ V,
                                             float* __restrict__ O)
{
    __shared__ __nv_bfloat16 As[BM * LDA];    // E tile 128 x 32
    __shared__ __nv_bfloat16 Bs[BK * LDB2];   // scaled V tile 32 x 128

    const int batch = blockIdx.y;
    const int it = blockIdx.x >> 2;
    const int jt = blockIdx.x & 3;
    const __nv_bfloat16* Eb = g_E + (size_t)batch * SDIM * SDIM + (size_t)(it * BM) * SDIM;
    const float* Vb = V + (size_t)batch * SDIM * SDIM + jt * BN;
    const float* zinv = g_Zinv[batch];

    const int tid = threadIdx.x;
    const int wid = tid >> 5;
    const int wr = wid & 3;
    const int wc = wid >> 2;

    wmma::fragment<wmma::accumulator, 16, 16, 16, float> acc[2][4];
#pragma unroll
    for (int a = 0; a < 2; a++)
#pragma unroll
        for (int b = 0; b < 4; b++) wmma::fill_fragment(acc[a][b], 0.0f);

    for (int kk = 0; kk < SDIM; kk += BK) {
        // load E tile: 128 rows x 32 bf16 (uint4 = 8 bf16)
#pragma unroll
        for (int i = 0; i < 2; i++) {
            int row = (tid >> 2) + i * 64;
            int c8 = (tid & 3) * 8;
            uint4 ev = *(const uint4*)(Eb + (size_t)row * SDIM + kk + c8);
            *(uint4*)(As + row * LDA + c8) = ev;
        }
        // load V tile: 32 k-rows x 128 j-cols fp32, scale by zinv[k], -> bf16
        {
            int k = tid >> 3;
            float zi = zinv[kk + k];
#pragma unroll
            for (int i = 0; i < 4; i++) {
                int j = ((tid & 7) + i * 8) * 4;
                float4 v = *(const float4*)(Vb + (size_t)(kk + k) * SDIM + j);
                __nv_bfloat16* pb = Bs + k * LDB2 + j;
                pb[0] = __float2bfloat16(v.x * zi);
                pb[1] = __float2bfloat16(v.y * zi);
                pb[2] = __float2bfloat16(v.z * zi);
                pb[3] = __float2bfloat16(v.w * zi);
            }
        }
        __syncthreads();
#pragma unroll
        for (int ks = 0; ks < BK; ks += 16) {
            wmma::fragment<wmma::matrix_a, 16, 16, 16, __nv_bfloat16, wmma::row_major> af[2];
            wmma::fragment<wmma::matrix_b, 16, 16, 16, __nv_bfloat16, wmma::row_major> bf[4];
#pragma unroll
            for (int a = 0; a < 2; a++)
                wmma::load_matrix_sync(af[a], As + (wr * 32 + a * 16) * LDA + ks, LDA);
#pragma unroll
            for (int b = 0; b < 4; b++)
                wmma::load_matrix_sync(bf[b], Bs + ks * LDB2 + wc * 64 + b * 16, LDB2);
#pragma unroll
            for (int a = 0; a < 2; a++)
#pragma unroll
                for (int b = 0; b < 4; b++)
                    wmma::mma_sync(acc[a][b], af[a], bf[b], acc[a][b]);
        }
        __syncthreads();
    }

    float* Ob = O + (size_t)batch * SDIM * SDIM + (size_t)(it * BM) * SDIM + jt * BN;
#pragma unroll
    for (int a = 0; a < 2; a++)
#pragma unroll
        for (int b = 0; b < 4; b++)
            wmma::store_matrix_sync(Ob + (size_t)(wr * 32 + a * 16) * SDIM + wc * 64 + b * 16,
                                    acc[a][b], SDIM, wmma::mem_row_major);
}

// ---------------------------------------------------------------------------
// Launch. Inputs per metadata order: d_in[0]=x1 (unused), [1]=query, [2]=key,
// [3]=value. Output fp32 [128,4,512,512].
// ---------------------------------------------------------------------------
extern "C" void kernel_launch(void* const* d_in, const int* in_sizes, int n_in,
                              void* d_out, int out_size)
{
    (void)in_sizes; (void)n_in; (void)out_size;
    const float* Q = (const float*)d_in[1];
    const float* K = (const float*)d_in[2];
    const float* V = (const float*)d_in[3];
    float* out = (float*)d_out;

    const int k1_smem = BM * LDC * (int)sizeof(float);   // 67584 > 48K -> opt-in
    cudaFuncSetAttribute(k1_qk_exp, cudaFuncAttributeMaxDynamicSharedMemorySize, k1_smem);

    dim3 grid(16, NBATCH);
    k1_qk_exp<<<grid, 256, k1_smem>>>(Q, K);
    k_zred<<<NBATCH, SDIM>>>();
    k2_pv<<<grid, 256>>>(V, out);
}